// round 12
// baseline (speedup 1.0000x reference)
#include <cuda_runtime.h>

// HH_Gap: B=16, N=4096, L=512. TWO independent trajectories per thread
// (ILP=2) to fill per-warp dependency-stall cycles. Per-trajectory
// arithmetic FROZEN (XLA:CPU aarch64 emulation, rel_err 4.920904e-4):
// Eigen Cephes pexp via fma, single-use-left FMA contraction, FCHK-free
// correctly-rounded div, hoisted constant-denominator reciprocals,
// magic-add ldexp, approx output sigmoid (off the amplified path).

#define NSTEPS 4096
#define BB 16
#define LL 512
#define NTRAJ (BB * LL)          // 8192
#define NTHREADS (NTRAJ / 2)     // 4096

__device__ __forceinline__ float fm(float a, float b) { return __fmul_rn(a, b); }
__device__ __forceinline__ float fa(float a, float b) { return __fadd_rn(a, b); }
__device__ __forceinline__ float ff(float a, float b, float c) { return __fmaf_rn(a, b, c); }

__device__ __forceinline__ float rcp_ref(float b) {
    float r;
    asm("rcp.approx.f32 %0, %1;" : "=f"(r) : "f"(b));
    float e = __fmaf_rn(-b, r, 1.0f);
    return __fmaf_rn(r, e, r);
}
__device__ __forceinline__ float fdc(float a, float b, float rp) {
    float q = __fmul_rn(a, rp);
    float rem = __fmaf_rn(-b, q, a);
    return __fmaf_rn(rem, rp, q);
}
__device__ __forceinline__ float fd(float a, float b) {
    return fdc(a, b, rcp_ref(b));
}

// Eigen/XLA-CPU pexp_float (Cephes), bit-exact; ldexp via exact magic-add.
__device__ __forceinline__ float eigen_expf(float x) {
    float m = floorf(ff(x, 1.44269504088896341f, 0.5f));
    float r = ff(m, -0.693359375f, x);
    r = ff(m, 2.12194440e-4f, r);
    float r2 = fm(r, r);
    float r3 = fm(r2, r);
    float y  = ff(1.9875691500e-4f, r, 1.3981999507e-3f);
    float y1 = ff(4.1665795894e-2f, r, 1.6666665459e-1f);
    float y2 = fa(r, 1.0f);
    y  = ff(y, r, 8.3334519073e-3f);
    y1 = ff(y1, r, 5.0000001201e-1f);
    y  = ff(y, r3, y1);
    y  = ff(y, r2, y2);
    float tmag = fa(m, 12582912.0f);               // 2^23 + 2^22, exact
    int sbits = (__float_as_int(tmag) + 127 - 0x4B400000) << 23;
    return fm(y, __int_as_float(sbits));
}

// Output sigmoid: not in the recurrence; approx ex2/rcp (~2e-7) invisible
// at the 4.92e-4 floor.
__device__ __forceinline__ float out_sigmoid(float V) {
    const float k = 0.4808983469629878f;           // log2(e)/3
    float a = ff(V, -k, -9.617966939259756f);
    float e2, rr;
    asm("ex2.approx.f32 %0, %1;" : "=f"(e2) : "f"(a));
    float d = fa(1.0f, e2);
    asm("rcp.approx.f32 %0, %1;" : "=f"(rr) : "f"(d));
    return rr;
}

// One HH Crank-Nicolson step (frozen arithmetic). Returns output sigmoid.
__device__ __forceinline__ float hh_step(float& V, float& m, float& n, float& h,
                                         float zprev, float r9, float r12, float r197) {
    float mm   = fm(m, m);
    float m3   = fm(m, mm);
    float pow1 = fm(fm(40.0f, m3), h);
    float nn   = fm(n, n);
    float n4   = fm(nn, nn);
    float pow2 = fm(35.0f, n4);

    float S  = fa(fa(pow1, pow2), 0.3f);
    float G  = fm(0.025f, S);
    float oneMinusG = fa(1.0f, -G);
    float onePlusG  = fa(1.0f, G);
    float E  = fa(ff(pow1, 55.0f, fm(pow2, -77.0f)), -19.5f);
    float EZ = fa(E, zprev);
    float num = ff(V, oneMinusG, fm(0.05f, EZ));
    float Vn  = fd(num, onePlusG);

    float vm25 = fa(Vn, -25.0f);
    float vp35 = fa(Vn, 35.0f);
    float d25  = fdc(vm25, 9.0f, r9);
    float d9v  = fdc(vp35, 9.0f, r9);
    float d90  = fdc(fa(Vn, 90.0f), 12.0f, r12);
    float d70  = fdc(fa(Vn, -70.0f), 19.7f, r197);
    float d34  = fdc(fa(Vn, 34.0f), 12.0f, r12);

    float eN  = eigen_expf(-d25);
    float eM  = eigen_expf(-d9v);
    float eB  = eigen_expf(d9v);
    float eAH = eigen_expf(-d90);
    float eBN = eigen_expf(-d70);
    float eBH = eigen_expf(d34);

    float dN = fa(1.0f, -eN);
    float aN = (dN == 0.0f) ? 0.18f : fd(fm(0.02f, vm25), dN);
    float dM = fa(1.0f, -eM);
    float aM = (dM == 0.0f) ? 1.638f : fd(fm(0.182f, vp35), dM);
    float aH = fm(0.25f, eAH);
    float dB = fa(1.0f, -eB);
    float bM = (dB == 0.0f) ? 1.116f : fd(fm(-0.124f, vp35), dB);

    float ABm = fa(aM, bM);
    float sM  = fm(0.025f, ABm);
    float umM = fa(1.0f, -sM);
    float dmM = fa(sM, 1.0f);
    m = fd(ff(aM, 0.05f, fm(umM, m)), dmM);

    float ABn = ff(0.125f, eBN, aN);
    float sN  = fm(0.025f, ABn);
    float umN = fa(1.0f, -sN);
    float dmN = fa(sN, 1.0f);
    n = fd(ff(aN, 0.05f, fm(umN, n)), dmN);

    float ABh = ff(0.25f, eBH, aH);
    float sH  = fm(0.025f, ABh);
    float umH = fa(1.0f, -sH);
    float dmH = fa(sH, 1.0f);
    h = fd(ff(aH, 0.05f, fm(umH, h)), dmH);

    V = Vn;
    return out_sigmoid(Vn);
}

__global__ __launch_bounds__(64, 1)
void hh_gap_kernel(const float* __restrict__ z, float* __restrict__ out) {
    int tid = blockIdx.x * blockDim.x + threadIdx.x;   // 0..4095
    // Trajectory pair: t0 = tid, t1 = tid + 4096 (both lane-coalesced)
    const float* zp0 = z   + (size_t)tid * 1 + (size_t)(tid >> 9) * (NSTEPS - 1) * LL;
    // simpler: recompute from (b,l)
    int b0 = tid >> 9,           l0 = tid & (LL - 1);
    int t1 = tid + NTHREADS;
    int b1 = t1 >> 9,            l1 = t1 & (LL - 1);
    zp0              = z   + (size_t)b0 * NSTEPS * LL + l0;
    const float* zp1 = z   + (size_t)b1 * NSTEPS * LL + l1;
    float* op0       = out + (size_t)b0 * NSTEPS * LL + l0;
    float* op1       = out + (size_t)b1 * NSTEPS * LL + l1;

    const float r9   = rcp_ref(9.0f);
    const float r12  = rcp_ref(12.0f);
    const float r197 = rcp_ref(19.7f);

    float V0 = -70.0f, m0 = 0.0f, n0 = 0.0f, h0 = 1.0f;
    float V1 = -70.0f, m1 = 0.0f, n1 = 0.0f, h1 = 1.0f;

    op0[0] = out_sigmoid(V0);
    op1[0] = out_sigmoid(V1);

    float zbuf0[8], zbuf1[8];
#pragma unroll
    for (int i = 0; i < 8; ++i) {
        zbuf0[i] = __ldcg(zp0 + i * LL);
        zbuf1[i] = __ldcg(zp1 + i * LL);
    }

    for (int t = 0; t < NSTEPS / 8; ++t) {
#pragma unroll
        for (int j = 0; j < 8; ++j) {
            int kz = t * 8 + j;
            float zprev0 = zbuf0[j];
            float zprev1 = zbuf1[j];
            int pidx = kz + 8;
            if (pidx < NSTEPS - 1) {
                zbuf0[j] = __ldcg(zp0 + (size_t)pidx * LL);
                zbuf1[j] = __ldcg(zp1 + (size_t)pidx * LL);
            }

            // Two independent steps — compiler interleaves for ILP.
            float y0 = hh_step(V0, m0, n0, h0, zprev0, r9, r12, r197);
            float y1 = hh_step(V1, m1, n1, h1, zprev1, r9, r12, r197);

            if (kz < NSTEPS - 1) {
                __stcs(op0 + (size_t)(kz + 1) * LL, y0);
                __stcs(op1 + (size_t)(kz + 1) * LL, y1);
            }
        }
    }
}

extern "C" void kernel_launch(void* const* d_in, const int* in_sizes, int n_in,
                              void* d_out, int out_size) {
    const float* z = (const float*)d_in[0];
    float* out = (float*)d_out;
    (void)in_sizes; (void)n_in; (void)out_size;
    hh_gap_kernel<<<NTHREADS / 64, 64>>>(z, out);
}

// round 13
// speedup vs baseline: 1.9455x; 1.9455x over previous
#include <cuda_runtime.h>

// HH_Gap: B=16, N=4096, L=512. Two trajectories per thread, PACKED into
// f32x2 lanes (fma/add/mul.rn.f32x2 = SASS FFMA2): per-lane IEEE-rn ops are
// bit-identical to the frozen scalar arithmetic (XLA:CPU aarch64 emulation,
// rel_err 4.920904e-4), but halve the fma-pipe instruction count that bounds
// a single in-order warp (FFMA rt_SMSP=2). MUFU/floor/int/guards stay scalar
// per lane. 4096 threads, 64 blocks x 64.

typedef unsigned long long u64;

#define NSTEPS 4096
#define LL 512
#define NTHREADS 4096

__device__ __forceinline__ float fa_(float a, float b) { return __fadd_rn(a, b); }
__device__ __forceinline__ float ff_(float a, float b, float c) { return __fmaf_rn(a, b, c); }

__device__ __forceinline__ u64 pk(float lo, float hi) {
    u64 d; asm("mov.b64 %0, {%1, %2};" : "=l"(d) : "f"(lo), "f"(hi)); return d;
}
__device__ __forceinline__ void upk(float& lo, float& hi, u64 d) {
    asm("mov.b64 {%0, %1}, %2;" : "=f"(lo), "=f"(hi) : "l"(d));
}
__device__ __forceinline__ u64 mul2(u64 a, u64 b) {
    u64 d; asm("mul.rn.f32x2 %0, %1, %2;" : "=l"(d) : "l"(a), "l"(b)); return d;
}
__device__ __forceinline__ u64 add2(u64 a, u64 b) {
    u64 d; asm("add.rn.f32x2 %0, %1, %2;" : "=l"(d) : "l"(a), "l"(b)); return d;
}
__device__ __forceinline__ u64 fma2(u64 a, u64 b, u64 c) {
    u64 d; asm("fma.rn.f32x2 %0, %1, %2, %3;" : "=l"(d) : "l"(a), "l"(b), "l"(c)); return d;
}
__device__ __forceinline__ u64 neg2(u64 a) { return a ^ 0x8000000080000000ULL; }
__device__ __forceinline__ float rcpa(float x) {
    float r; asm("rcp.approx.f32 %0, %1;" : "=f"(r) : "f"(x)); return r;
}
__device__ __forceinline__ float ex2a(float x) {
    float r; asm("ex2.approx.f32 %0, %1;" : "=f"(r) : "f"(x)); return r;
}
__device__ __forceinline__ u64 cpair(float c) { return pk(c, c); }

// Packed correctly-rounded division (FCHK-free fast path, per-lane identical
// to scalar sequence).
__device__ __forceinline__ u64 div2(u64 a, u64 b) {
    float b0, b1; upk(b0, b1, b);
    u64 r = pk(rcpa(b0), rcpa(b1));
    u64 nb = neg2(b);
    u64 one = cpair(1.0f);
    u64 e = fma2(nb, r, one);
    r = fma2(r, e, r);
    u64 q = mul2(a, r);
    u64 rem = fma2(nb, q, a);
    return fma2(rem, r, q);
}
// Packed const-denominator division: nb = (-b,-b), rp = refined rcp pair.
__device__ __forceinline__ u64 fdc2(u64 a, u64 nb, u64 rp) {
    u64 q = mul2(a, rp);
    u64 rem = fma2(nb, q, a);
    return fma2(rem, rp, q);
}
__device__ __forceinline__ float rcp_ref(float b) {
    float r = rcpa(b);
    float e = __fmaf_rn(-b, r, 1.0f);
    return __fmaf_rn(r, e, r);
}

// Packed Eigen/XLA-CPU Cephes pexp: per-lane bit-identical to scalar version.
__device__ __forceinline__ u64 eexp2(u64 x) {
    u64 t = fma2(x, cpair(1.44269504088896341f), cpair(0.5f));
    float t0, t1; upk(t0, t1, t);
    float mf0 = floorf(t0), mf1 = floorf(t1);
    u64 mv = pk(mf0, mf1);
    u64 r = fma2(mv, cpair(-0.693359375f), x);
    r = fma2(mv, cpair(2.12194440e-4f), r);
    u64 r2 = mul2(r, r);
    u64 r3 = mul2(r2, r);
    u64 y  = fma2(cpair(1.9875691500e-4f), r, cpair(1.3981999507e-3f));
    u64 y1 = fma2(cpair(4.1665795894e-2f), r, cpair(1.6666665459e-1f));
    u64 y2 = add2(r, cpair(1.0f));
    y  = fma2(y, r, cpair(8.3334519073e-3f));
    y1 = fma2(y1, r, cpair(5.0000001201e-1f));
    y  = fma2(y, r3, y1);
    y  = fma2(y, r2, y2);
    float tm0 = fa_(mf0, 12582912.0f);
    float tm1 = fa_(mf1, 12582912.0f);
    int s0 = (__float_as_int(tm0) + 127 - 0x4B400000) << 23;
    int s1 = (__float_as_int(tm1) + 127 - 0x4B400000) << 23;
    u64 sv = pk(__int_as_float(s0), __int_as_float(s1));
    return mul2(y, sv);
}

// Output sigmoid per lane (off the amplified path; approx ok at 4.92e-4 floor)
__device__ __forceinline__ float out_sig(float V) {
    float a = ff_(V, -0.4808983469629878f, -9.617966939259756f);
    return rcpa(fa_(1.0f, ex2a(a)));
}

__global__ __launch_bounds__(64, 1)
void hh_gap_kernel(const float* __restrict__ z, float* __restrict__ out) {
    int tid = blockIdx.x * blockDim.x + threadIdx.x;   // 0..4095
    int b0 = tid >> 9, l0 = tid & (LL - 1);
    int t1 = tid + NTHREADS;
    int b1 = t1 >> 9, l1 = t1 & (LL - 1);
    const float* zp0 = z   + (size_t)b0 * NSTEPS * LL + l0;
    const float* zp1 = z   + (size_t)b1 * NSTEPS * LL + l1;
    float* op0       = out + (size_t)b0 * NSTEPS * LL + l0;
    float* op1       = out + (size_t)b1 * NSTEPS * LL + l1;

    // hoisted constant-denominator reciprocal pairs
    const u64 rp9  = cpair(rcp_ref(9.0f)),  nb9  = cpair(-9.0f);
    const u64 rp12 = cpair(rcp_ref(12.0f)), nb12 = cpair(-12.0f);
    const u64 rp197 = cpair(rcp_ref(19.7f)), nb197 = cpair(-19.7f);
    const u64 one = cpair(1.0f), m1 = cpair(-1.0f);

    u64 V = cpair(-70.0f), m = cpair(0.0f), n = cpair(0.0f), h = cpair(1.0f);

    op0[0] = out_sig(-70.0f);
    op1[0] = out_sig(-70.0f);

    float zb0[4], zb1[4];
#pragma unroll
    for (int i = 0; i < 4; ++i) {
        zb0[i] = __ldcg(zp0 + i * LL);
        zb1[i] = __ldcg(zp1 + i * LL);
    }

    for (int t = 0; t < NSTEPS / 4; ++t) {
#pragma unroll
        for (int j = 0; j < 4; ++j) {
            int kz = t * 4 + j;
            u64 zv = pk(zb0[j], zb1[j]);
            int pidx = kz + 4;
            if (pidx < NSTEPS - 1) {
                zb0[j] = __ldcg(zp0 + (size_t)pidx * LL);
                zb1[j] = __ldcg(zp1 + (size_t)pidx * LL);
            }

            // ---- V update ----
            u64 mm   = mul2(m, m);
            u64 m3   = mul2(m, mm);
            u64 pow1 = mul2(mul2(cpair(40.0f), m3), h);
            u64 nn   = mul2(n, n);
            u64 n4   = mul2(nn, nn);
            u64 pow2 = mul2(cpair(35.0f), n4);
            u64 S    = add2(add2(pow1, pow2), cpair(0.3f));
            u64 G    = mul2(cpair(0.025f), S);
            u64 oneMinusG = fma2(G, m1, one);      // == fadd(1,-G) bitwise
            u64 onePlusG  = add2(one, G);
            u64 E  = add2(fma2(pow1, cpair(55.0f), mul2(pow2, cpair(-77.0f))),
                          cpair(-19.5f));
            u64 EZ = add2(E, zv);
            u64 num = fma2(V, oneMinusG, mul2(cpair(0.05f), EZ));
            u64 Vn  = div2(num, onePlusG);

            // ---- exp args ----
            u64 vm25 = add2(Vn, cpair(-25.0f));
            u64 vp35 = add2(Vn, cpair(35.0f));
            u64 d25 = fdc2(vm25, nb9, rp9);
            u64 d9v = fdc2(vp35, nb9, rp9);
            u64 d90 = fdc2(add2(Vn, cpair(90.0f)), nb12, rp12);
            u64 d70 = fdc2(add2(Vn, cpair(-70.0f)), nb197, rp197);
            u64 d34 = fdc2(add2(Vn, cpair(34.0f)), nb12, rp12);

            u64 eN  = eexp2(neg2(d25));
            u64 eM  = eexp2(neg2(d9v));
            u64 eB  = eexp2(d9v);
            u64 eAH = eexp2(neg2(d90));
            u64 eBN = eexp2(neg2(d70));
            u64 eBH = eexp2(d34);

            // ---- rates with per-lane guards ----
            u64 dN = fma2(eN, m1, one);            // 1 - eN
            u64 aN = div2(mul2(cpair(0.02f), vm25), dN);
            { float g0,g1,q0,q1; upk(q0,q1,dN); upk(g0,g1,aN);
              g0 = (q0==0.0f)?0.18f:g0; g1 = (q1==0.0f)?0.18f:g1; aN = pk(g0,g1); }
            u64 dM = fma2(eM, m1, one);
            u64 aM = div2(mul2(cpair(0.182f), vp35), dM);
            { float g0,g1,q0,q1; upk(q0,q1,dM); upk(g0,g1,aM);
              g0 = (q0==0.0f)?1.638f:g0; g1 = (q1==0.0f)?1.638f:g1; aM = pk(g0,g1); }
            u64 dB = fma2(eB, m1, one);
            u64 bM = div2(mul2(cpair(-0.124f), vp35), dB);
            { float g0,g1,q0,q1; upk(q0,q1,dB); upk(g0,g1,bM);
              g0 = (q0==0.0f)?1.116f:g0; g1 = (q1==0.0f)?1.116f:g1; bM = pk(g0,g1); }
            u64 aH = mul2(cpair(0.25f), eAH);

            // ---- CN gate updates ----
            u64 ABm = add2(aM, bM);
            u64 sM  = mul2(cpair(0.025f), ABm);
            u64 umM = fma2(sM, m1, one);
            u64 dmM = add2(sM, one);
            m = div2(fma2(aM, cpair(0.05f), mul2(umM, m)), dmM);

            u64 ABn = fma2(cpair(0.125f), eBN, aN);
            u64 sN  = mul2(cpair(0.025f), ABn);
            u64 umN = fma2(sN, m1, one);
            u64 dmN = add2(sN, one);
            n = div2(fma2(aN, cpair(0.05f), mul2(umN, n)), dmN);

            u64 ABh = fma2(cpair(0.25f), eBH, aH);
            u64 sH  = mul2(cpair(0.025f), ABh);
            u64 umH = fma2(sH, m1, one);
            u64 dmH = add2(sH, one);
            h = div2(fma2(aH, cpair(0.05f), mul2(umH, h)), dmH);

            V = Vn;

            // ---- output (scalar per lane) ----
            float v0, v1; upk(v0, v1, Vn);
            float y0 = out_sig(v0);
            float y1 = out_sig(v1);
            if (kz < NSTEPS - 1) {
                __stcs(op0 + (size_t)(kz + 1) * LL, y0);
                __stcs(op1 + (size_t)(kz + 1) * LL, y1);
            }
        }
    }
}

extern "C" void kernel_launch(void* const* d_in, const int* in_sizes, int n_in,
                              void* d_out, int out_size) {
    const float* z = (const float*)d_in[0];
    float* out = (float*)d_out;
    (void)in_sizes; (void)n_in; (void)out_size;
    hh_gap_kernel<<<NTHREADS / 64, 64>>>(z, out);
}

// round 14
// speedup vs baseline: 2.5253x; 1.2980x over previous
#include <cuda_runtime.h>

// HH_Gap: B=16, N=4096, L=512. ONE trajectory per thread (8192 threads,
// the R11 threading that won), with f32x2 packing of INDEPENDENT ops inside
// each step: 6 exps -> 3 packed, m/n powers, /9 & /12 arg-divs, aN/aM rate
// divs, m/n gate updates. Per-lane f32x2 rn ops are bit-identical to the
// frozen scalar arithmetic (XLA:CPU aarch64 emulation, rel_err 4.920904e-4);
// this halves the warp's FFMA issue count that floors single-warp latency.

typedef unsigned long long u64;

#define NSTEPS 4096
#define LL 512
#define NTHREADS 8192

__device__ __forceinline__ float fm(float a, float b) { return __fmul_rn(a, b); }
__device__ __forceinline__ float fa(float a, float b) { return __fadd_rn(a, b); }
__device__ __forceinline__ float ff(float a, float b, float c) { return __fmaf_rn(a, b, c); }

__device__ __forceinline__ u64 pk(float lo, float hi) {
    u64 d; asm("mov.b64 %0, {%1, %2};" : "=l"(d) : "f"(lo), "f"(hi)); return d;
}
__device__ __forceinline__ void upk(float& lo, float& hi, u64 d) {
    asm("mov.b64 {%0, %1}, %2;" : "=f"(lo), "=f"(hi) : "l"(d));
}
__device__ __forceinline__ u64 mul2(u64 a, u64 b) {
    u64 d; asm("mul.rn.f32x2 %0, %1, %2;" : "=l"(d) : "l"(a), "l"(b)); return d;
}
__device__ __forceinline__ u64 add2(u64 a, u64 b) {
    u64 d; asm("add.rn.f32x2 %0, %1, %2;" : "=l"(d) : "l"(a), "l"(b)); return d;
}
__device__ __forceinline__ u64 fma2(u64 a, u64 b, u64 c) {
    u64 d; asm("fma.rn.f32x2 %0, %1, %2, %3;" : "=l"(d) : "l"(a), "l"(b), "l"(c)); return d;
}
__device__ __forceinline__ u64 neg2(u64 a) { return a ^ 0x8000000080000000ULL; }
__device__ __forceinline__ float rcpa(float x) {
    float r; asm("rcp.approx.f32 %0, %1;" : "=f"(r) : "f"(x)); return r;
}
__device__ __forceinline__ float ex2a(float x) {
    float r; asm("ex2.approx.f32 %0, %1;" : "=f"(r) : "f"(x)); return r;
}
__device__ __forceinline__ u64 cpair(float c) { return pk(c, c); }

// Packed correctly-rounded division (FCHK-free fast path; per-lane identical
// to the frozen scalar sequence).
__device__ __forceinline__ u64 div2(u64 a, u64 b) {
    float b0, b1; upk(b0, b1, b);
    u64 r = pk(rcpa(b0), rcpa(b1));
    u64 nb = neg2(b);
    u64 one = cpair(1.0f);
    u64 e = fma2(nb, r, one);
    r = fma2(r, e, r);
    u64 q = mul2(a, r);
    u64 rem = fma2(nb, q, a);
    return fma2(rem, r, q);
}
// Packed const-denominator division (hoisted refined reciprocal pair).
__device__ __forceinline__ u64 fdc2(u64 a, u64 nb, u64 rp) {
    u64 q = mul2(a, rp);
    u64 rem = fma2(nb, q, a);
    return fma2(rem, rp, q);
}
__device__ __forceinline__ float rcp_ref(float b) {
    float r = rcpa(b);
    float e = __fmaf_rn(-b, r, 1.0f);
    return __fmaf_rn(r, e, r);
}
// Scalar correctly-rounded division.
__device__ __forceinline__ float fdiv(float a, float b) {
    float r = rcp_ref(b);
    float q = __fmul_rn(a, r);
    float rem = __fmaf_rn(-b, q, a);
    return __fmaf_rn(rem, r, q);
}

// Packed Eigen/XLA-CPU Cephes pexp (per-lane bit-identical to scalar).
__device__ __forceinline__ u64 eexp2(u64 x) {
    u64 t = fma2(x, cpair(1.44269504088896341f), cpair(0.5f));
    float t0, t1; upk(t0, t1, t);
    u64 mv = pk(floorf(t0), floorf(t1));
    u64 r = fma2(mv, cpair(-0.693359375f), x);
    r = fma2(mv, cpair(2.12194440e-4f), r);
    u64 r2 = mul2(r, r);
    u64 r3 = mul2(r2, r);
    u64 y  = fma2(cpair(1.9875691500e-4f), r, cpair(1.3981999507e-3f));
    u64 y1 = fma2(cpair(4.1665795894e-2f), r, cpair(1.6666665459e-1f));
    u64 y2 = add2(r, cpair(1.0f));
    y  = fma2(y, r, cpair(8.3334519073e-3f));
    y1 = fma2(y1, r, cpair(5.0000001201e-1f));
    y  = fma2(y, r3, y1);
    y  = fma2(y, r2, y2);
    u64 tm = add2(mv, cpair(12582912.0f));          // exact magic-add
    float tma, tmb; upk(tma, tmb, tm);
    int s0 = (__float_as_int(tma) + 127 - 0x4B400000) << 23;
    int s1 = (__float_as_int(tmb) + 127 - 0x4B400000) << 23;
    return mul2(y, pk(__int_as_float(s0), __int_as_float(s1)));
}

// Output sigmoid (off the amplified path; approx ok at the 4.92e-4 floor).
__device__ __forceinline__ float out_sig(float V) {
    float a = ff(V, -0.4808983469629878f, -9.617966939259756f);
    return rcpa(fa(1.0f, ex2a(a)));
}

__global__ __launch_bounds__(64, 1)
void hh_gap_kernel(const float* __restrict__ z, float* __restrict__ out) {
    int tid = blockIdx.x * blockDim.x + threadIdx.x;   // 0..8191
    int b = tid >> 9;
    int l = tid & (LL - 1);
    const float* zp = z   + (size_t)b * NSTEPS * LL + l;
    float*       op = out + (size_t)b * NSTEPS * LL + l;

    const u64 rp9   = cpair(rcp_ref(9.0f)),  nb9  = cpair(-9.0f);
    const u64 rp12  = cpair(rcp_ref(12.0f)), nb12 = cpair(-12.0f);
    const float r197 = rcp_ref(19.7f);
    const u64 one = cpair(1.0f), mone = cpair(-1.0f);

    float V = -70.0f, h = 1.0f;
    u64 mn = pk(0.0f, 0.0f);                 // (m, n) packed state

    op[0] = out_sig(V);

    float zbuf[4];
#pragma unroll
    for (int i = 0; i < 4; ++i) zbuf[i] = __ldcg(zp + i * LL);

    for (int t = 0; t < NSTEPS / 4; ++t) {
#pragma unroll
        for (int j = 0; j < 4; ++j) {
            int kz = t * 4 + j;
            float zprev = zbuf[j];
            int pidx = kz + 4;
            if (pidx < NSTEPS - 1) zbuf[j] = __ldcg(zp + (size_t)pidx * LL);

            // ---- powers: (m,n) packed ----
            float mlo, nlo; upk(mlo, nlo, mn);
            u64 mm_nn = mul2(mn, mn);                      // (m*m, n*n)
            float mm, nn; upk(mm, nn, mm_nn);
            u64 m3_n4 = mul2(pk(mlo, nn), pk(mm, nn));     // (m3, n4)
            u64 pp    = mul2(pk(40.0f, 35.0f), m3_n4);     // (40m3, 35n4)
            u64 pow12 = mul2(pp, pk(h, 1.0f));             // (*h, *1: exact)
            float pow1, pow2; upk(pow1, pow2, pow12);

            float S  = fa(fa(pow1, pow2), 0.3f);
            float G  = fm(0.025f, S);
            float oneMinusG = fa(1.0f, -G);
            float onePlusG  = fa(1.0f, G);
            float E  = fa(ff(pow1, 55.0f, fm(pow2, -77.0f)), -19.5f);
            float EZ = fa(E, zprev);
            float num = ff(V, oneMinusG, fm(0.05f, EZ));
            float Vn  = fdiv(num, onePlusG);

            // ---- exp args: pack by shared denominator ----
            u64 VnVn = pk(Vn, Vn);
            u64 v25_35 = add2(VnVn, pk(-25.0f, 35.0f));    // (Vn-25, Vn+35)
            u64 d25_9v = fdc2(v25_35, nb9, rp9);
            u64 v90_34 = add2(VnVn, pk(90.0f, 34.0f));
            u64 d90_34 = fdc2(v90_34, nb12, rp12);
            float v70 = fa(Vn, -70.0f);
            float q70 = __fmul_rn(v70, r197);
            float rem70 = __fmaf_rn(-19.7f, q70, v70);
            float d70 = __fmaf_rn(rem70, r197, q70);

            float d25, d9v; upk(d25, d9v, d25_9v);
            float d90, d34; upk(d90, d34, d90_34);

            // ---- 3 packed exps (6 values) ----
            u64 eNM   = eexp2(neg2(d25_9v));               // (eN,  eM)
            u64 eB_AH = eexp2(pk(d9v, -d90));              // (eB,  eAH)
            u64 eBNBH = eexp2(pk(-d70, d34));              // (eBN, eBH)

            // ---- rates: aN/aM packed div, bM scalar ----
            u64 dNM = fma2(eNM, mone, one);                // (1-eN, 1-eM)
            u64 ratnum = mul2(pk(0.02f, 0.182f), v25_35);
            u64 aNM = div2(ratnum, dNM);
            float dN, dM; upk(dN, dM, dNM);
            float aN, aM; upk(aN, aM, aNM);
            aN = (dN == 0.0f) ? 0.18f  : aN;
            aM = (dM == 0.0f) ? 1.638f : aM;
            float eB, eAH; upk(eB, eAH, eB_AH);
            float vm25, vp35; upk(vm25, vp35, v25_35);
            float dB = fa(1.0f, -eB);
            float bM = fdiv(fm(-0.124f, vp35), dB);
            bM = (dB == 0.0f) ? 1.116f : bM;
            float aH = fm(0.25f, eAH);
            float eBN, eBH; upk(eBN, eBH, eBNBH);

            // ---- CN gates: m,n packed; h scalar ----
            float ABm = fa(aM, bM);
            float ABn = ff(0.125f, eBN, aN);
            u64 AB  = pk(ABm, ABn);
            u64 s2  = mul2(cpair(0.025f), AB);
            u64 um2 = fma2(s2, mone, one);                 // == fa(1,-s) bitwise
            u64 dm2 = add2(s2, one);
            u64 gnum = fma2(pk(aM, aN), cpair(0.05f), mul2(um2, mn));
            mn = div2(gnum, dm2);

            float ABh = ff(0.25f, eBH, aH);
            float sH  = fm(0.025f, ABh);
            float umH = fa(1.0f, -sH);
            float dmH = fa(sH, 1.0f);
            h = fdiv(ff(aH, 0.05f, fm(umH, h)), dmH);

            V = Vn;

            float y = out_sig(Vn);
            if (kz < NSTEPS - 1) __stcs(op + (size_t)(kz + 1) * LL, y);
        }
    }
}

extern "C" void kernel_launch(void* const* d_in, const int* in_sizes, int n_in,
                              void* d_out, int out_size) {
    const float* z = (const float*)d_in[0];
    float* out = (float*)d_out;
    (void)in_sizes; (void)n_in; (void)out_size;
    hh_gap_kernel<<<NTHREADS / 64, 64>>>(z, out);
}

// round 16
// speedup vs baseline: 2.6734x; 1.0587x over previous
#include <cuda_runtime.h>

// HH_Gap: B=16, N=4096, L=512. One trajectory per thread (8192 threads),
// f32x2 packing of independent ops inside each step. Frozen arithmetic
// (XLA:CPU aarch64 emulation, rel_err 4.920904e-4). Round 16 (= R15 fixed):
//  * floorf in pexp -> __fadd_rd magic-add (exact; RD sum also supplies the
//    ldexp bit pattern directly, deleting the second magic-add)
//  * (S,E) and (1-G,1+G) packed via exact-product fma identities

typedef unsigned long long u64;

#define NSTEPS 4096
#define LL 512
#define NTHREADS 8192

__device__ __forceinline__ float fm(float a, float b) { return __fmul_rn(a, b); }
__device__ __forceinline__ float fa(float a, float b) { return __fadd_rn(a, b); }
__device__ __forceinline__ float ff(float a, float b, float c) { return __fmaf_rn(a, b, c); }

__device__ __forceinline__ u64 pk(float lo, float hi) {
    u64 d; asm("mov.b64 %0, {%1, %2};" : "=l"(d) : "f"(lo), "f"(hi)); return d;
}
__device__ __forceinline__ void upk(float& lo, float& hi, u64 d) {
    asm("mov.b64 {%0, %1}, %2;" : "=f"(lo), "=f"(hi) : "l"(d));
}
__device__ __forceinline__ u64 mul2(u64 a, u64 b) {
    u64 d; asm("mul.rn.f32x2 %0, %1, %2;" : "=l"(d) : "l"(a), "l"(b)); return d;
}
__device__ __forceinline__ u64 add2(u64 a, u64 b) {
    u64 d; asm("add.rn.f32x2 %0, %1, %2;" : "=l"(d) : "l"(a), "l"(b)); return d;
}
__device__ __forceinline__ u64 fma2(u64 a, u64 b, u64 c) {
    u64 d; asm("fma.rn.f32x2 %0, %1, %2, %3;" : "=l"(d) : "l"(a), "l"(b), "l"(c)); return d;
}
__device__ __forceinline__ u64 neg2(u64 a) { return a ^ 0x8000000080000000ULL; }
__device__ __forceinline__ float rcpa(float x) {
    float r; asm("rcp.approx.f32 %0, %1;" : "=f"(r) : "f"(x)); return r;
}
__device__ __forceinline__ float ex2a(float x) {
    float r; asm("ex2.approx.f32 %0, %1;" : "=f"(r) : "f"(x)); return r;
}
__device__ __forceinline__ u64 cpair(float c) { return pk(c, c); }

// Packed correctly-rounded division (FCHK-free fast path).
__device__ __forceinline__ u64 div2(u64 a, u64 b) {
    float b0, b1; upk(b0, b1, b);
    u64 r = pk(rcpa(b0), rcpa(b1));
    u64 nb = neg2(b);
    u64 one = cpair(1.0f);
    u64 e = fma2(nb, r, one);
    r = fma2(r, e, r);
    u64 q = mul2(a, r);
    u64 rem = fma2(nb, q, a);
    return fma2(rem, r, q);
}
// Packed const-denominator division (hoisted refined reciprocal pair).
__device__ __forceinline__ u64 fdc2(u64 a, u64 nb, u64 rp) {
    u64 q = mul2(a, rp);
    u64 rem = fma2(nb, q, a);
    return fma2(rem, rp, q);
}
__device__ __forceinline__ float rcp_ref(float b) {
    float r = rcpa(b);
    float e = __fmaf_rn(-b, r, 1.0f);
    return __fmaf_rn(r, e, r);
}
__device__ __forceinline__ float fdiv(float a, float b) {
    float r = rcp_ref(b);
    float q = __fmul_rn(a, r);
    float rem = __fmaf_rn(-b, q, a);
    return __fmaf_rn(rem, r, q);
}

// Packed Eigen/XLA-CPU Cephes pexp, bit-identical per lane.
// floor(t) via __fadd_rd magic (exact for |t| < 2^22); the RD sum IS the
// ldexp bit-source (floor(t) + 12582912), so no second magic-add.
__device__ __forceinline__ u64 eexp2(u64 x) {
    u64 t = fma2(x, cpair(1.44269504088896341f), cpair(0.5f));
    float t0, t1; upk(t0, t1, t);
    float trm0 = __fadd_rd(t0, 12582912.0f);
    float trm1 = __fadd_rd(t1, 12582912.0f);
    u64 mv = add2(pk(trm0, trm1), cpair(-12582912.0f));  // exact: == floor(t)
    u64 r = fma2(mv, cpair(-0.693359375f), x);
    r = fma2(mv, cpair(2.12194440e-4f), r);
    u64 r2 = mul2(r, r);
    u64 r3 = mul2(r2, r);
    u64 y  = fma2(cpair(1.9875691500e-4f), r, cpair(1.3981999507e-3f));
    u64 y1 = fma2(cpair(4.1665795894e-2f), r, cpair(1.6666665459e-1f));
    u64 y2 = add2(r, cpair(1.0f));
    y  = fma2(y, r, cpair(8.3334519073e-3f));
    y1 = fma2(y1, r, cpair(5.0000001201e-1f));
    y  = fma2(y, r3, y1);
    y  = fma2(y, r2, y2);
    int s0 = (__float_as_int(trm0) + 127 - 0x4B400000) << 23;
    int s1 = (__float_as_int(trm1) + 127 - 0x4B400000) << 23;
    return mul2(y, pk(__int_as_float(s0), __int_as_float(s1)));
}

// Output sigmoid (off the amplified path; approx ok at the 4.92e-4 floor).
__device__ __forceinline__ float out_sig(float V) {
    float a = ff(V, -0.4808983469629878f, -9.617966939259756f);
    return rcpa(fa(1.0f, ex2a(a)));
}

__global__ __launch_bounds__(64, 1)
void hh_gap_kernel(const float* __restrict__ z, float* __restrict__ out) {
    int tid = blockIdx.x * blockDim.x + threadIdx.x;   // 0..8191
    int b = tid >> 9;
    int l = tid & (LL - 1);
    const float* zp = z   + (size_t)b * NSTEPS * LL + l;
    float*       op = out + (size_t)b * NSTEPS * LL + l;

    const u64 rp9   = cpair(rcp_ref(9.0f)),  nb9  = cpair(-9.0f);
    const u64 rp12  = cpair(rcp_ref(12.0f)), nb12 = cpair(-12.0f);
    const float r197 = rcp_ref(19.7f);
    const u64 one = cpair(1.0f), mone = cpair(-1.0f);

    float V = -70.0f, h = 1.0f;
    u64 mn = pk(0.0f, 0.0f);                 // (m, n) packed state

    op[0] = out_sig(V);

    float zbuf[4];
#pragma unroll
    for (int i = 0; i < 4; ++i) zbuf[i] = __ldcg(zp + i * LL);

    for (int t = 0; t < NSTEPS / 4; ++t) {
#pragma unroll
        for (int j = 0; j < 4; ++j) {
            int kz = t * 4 + j;
            float zprev = zbuf[j];
            int pidx = kz + 4;
            if (pidx < NSTEPS - 1) zbuf[j] = __ldcg(zp + (size_t)pidx * LL);

            // ---- powers: (m,n) packed ----
            float mlo, nlo; upk(mlo, nlo, mn);
            u64 mm_nn = mul2(mn, mn);                      // (m*m, n*n)
            float mm, nn; upk(mm, nn, mm_nn);
            u64 m3_n4 = mul2(pk(mlo, nn), pk(mm, nn));     // (m3, n4)
            u64 pp    = mul2(pk(40.0f, 35.0f), m3_n4);     // (40m3, 35n4)
            u64 pow12 = mul2(pp, pk(h, 1.0f));             // (*h, *1: exact)
            float pow1, pow2; upk(pow1, pow2, pow12);

            // (S', E') packed: lane0 fma(pow1,1,pow2) == fadd(pow1,pow2)
            float p277 = fm(pow2, -77.0f);
            u64 SE = fma2(pk(pow1, pow1), pk(1.0f, 55.0f), pk(pow2, p277));
            SE = add2(SE, pk(0.3f, -19.5f));               // (S, E)
            float S, E; upk(S, E, SE);
            float G  = fm(0.025f, S);
            // (1-G, 1+G) packed: exact products
            u64 Gpm = fma2(pk(G, G), pk(-1.0f, 1.0f), one);
            float oneMinusG, onePlusG; upk(oneMinusG, onePlusG, Gpm);
            float EZ = fa(E, zprev);
            float num = ff(V, oneMinusG, fm(0.05f, EZ));
            float Vn  = fdiv(num, onePlusG);

            // ---- exp args: pack by shared denominator ----
            u64 VnVn = pk(Vn, Vn);
            u64 v25_35 = add2(VnVn, pk(-25.0f, 35.0f));    // (Vn-25, Vn+35)
            u64 d25_9v = fdc2(v25_35, nb9, rp9);
            u64 v90_34 = add2(VnVn, pk(90.0f, 34.0f));
            u64 d90_34 = fdc2(v90_34, nb12, rp12);
            float v70 = fa(Vn, -70.0f);
            float q70 = __fmul_rn(v70, r197);
            float rem70 = __fmaf_rn(-19.7f, q70, v70);
            float d70 = __fmaf_rn(rem70, r197, q70);

            float d25, d9v; upk(d25, d9v, d25_9v);
            float d90, d34; upk(d90, d34, d90_34);

            // ---- 3 packed exps (6 values) ----
            u64 eNM   = eexp2(neg2(d25_9v));               // (eN,  eM)
            u64 eB_AH = eexp2(pk(d9v, -d90));              // (eB,  eAH)
            u64 eBNBH = eexp2(pk(-d70, d34));              // (eBN, eBH)

            // ---- rates: aN/aM packed div, bM scalar ----
            u64 dNM = fma2(eNM, mone, one);                // (1-eN, 1-eM)
            u64 ratnum = mul2(pk(0.02f, 0.182f), v25_35);
            u64 aNM = div2(ratnum, dNM);
            float dN, dM; upk(dN, dM, dNM);
            float aN, aM; upk(aN, aM, aNM);
            aN = (dN == 0.0f) ? 0.18f  : aN;
            aM = (dM == 0.0f) ? 1.638f : aM;
            float eB, eAH; upk(eB, eAH, eB_AH);
            float vm25, vp35; upk(vm25, vp35, v25_35);
            float dB = fa(1.0f, -eB);
            float bM = fdiv(fm(-0.124f, vp35), dB);
            bM = (dB == 0.0f) ? 1.116f : bM;
            float aH = fm(0.25f, eAH);
            float eBN, eBH; upk(eBN, eBH, eBNBH);

            // ---- CN gates: m,n packed; h scalar ----
            float ABm = fa(aM, bM);
            float ABn = ff(0.125f, eBN, aN);
            u64 AB  = pk(ABm, ABn);
            u64 s2  = mul2(cpair(0.025f), AB);
            u64 um2 = fma2(s2, mone, one);                 // == fa(1,-s) bitwise
            u64 dm2 = add2(s2, one);
            u64 gnum = fma2(pk(aM, aN), cpair(0.05f), mul2(um2, mn));
            mn = div2(gnum, dm2);

            float ABh = ff(0.25f, eBH, aH);
            float sH  = fm(0.025f, ABh);
            float umH = fa(1.0f, -sH);
            float dmH = fa(sH, 1.0f);
            h = fdiv(ff(aH, 0.05f, fm(umH, h)), dmH);

            V = Vn;

            float y = out_sig(Vn);
            if (kz < NSTEPS - 1) __stcs(op + (size_t)(kz + 1) * LL, y);
        }
    }
}

extern "C" void kernel_launch(void* const* d_in, const int* in_sizes, int n_in,
                              void* d_out, int out_size) {
    const float* z = (const float*)d_in[0];
    float* out = (float*)d_out;
    (void)in_sizes; (void)n_in; (void)out_size;
    hh_gap_kernel<<<NTHREADS / 64, 64>>>(z, out);
}